// round 1
// baseline (speedup 1.0000x reference)
#include <cuda_runtime.h>
#include <math.h>

// Problem constants (fixed by the reference: HIDDEN_LAYERS = [4096]*4)
#define D    16384
#define B    8
#define H0   4096
#define BLK  4096

// GEMV tiling
#define K_TILE   256
#define THREADS  256
#define COLS_PER_THREAD 4
#define N_TILE   (THREADS * COLS_PER_THREAD)   // 1024
#define CTILES   (BLK / N_TILE)                // 4
#define KTILES   (BLK / K_TILE)                // 16
#define TILES_PER_PAIR (CTILES * KTILES)       // 64
#define NUM_PAIRS 6
#define GEMV_GRID (NUM_PAIRS * TILES_PER_PAIR) // 384

// Scratch (static __device__ — no allocation)
__device__ __align__(16) float g_rho_t[D * B];  // [d][b] transposed rho(s)
__device__ __align__(16) float g_acc[B * D];    // [b][d] accumulator

// ---------------------------------------------------------------------------
// Kernel 1: rho transpose + accumulator init (bias + input drive)
// ---------------------------------------------------------------------------
__global__ void prologue_kernel(const float* __restrict__ Ux,
                                const float* __restrict__ s,
                                const float* __restrict__ bias) {
    int idx = blockIdx.x * blockDim.x + threadIdx.x;
    if (idx >= D * B) return;
    int d = idx >> 3;       // 0..D-1
    int b = idx & 7;        // 0..7
    float sv = s[b * D + d];
    float r  = 1.0f / (1.0f + expf(-4.0f * (sv - 0.5f)));
    g_rho_t[d * B + b] = r;

    float a = bias[d];
    if (d < H0) a += Ux[b * H0 + d];
    g_acc[b * D + d] = a;
}

// ---------------------------------------------------------------------------
// Kernel 2: block-sparse batched GEMV mainloop
//   acc[b, n] += sum_k rho[b, k] * W[k, n]   over the 6 nonzero 4096x4096 blocks
// ---------------------------------------------------------------------------
__global__ void __launch_bounds__(THREADS) gemv_kernel(const float* __restrict__ W) {
    // Decode tile: pair p -> (rb, cb), then column tile ct, k tile kt
    int bid = blockIdx.x;
    int p = bid / TILES_PER_PAIR;
    int t = bid - p * TILES_PER_PAIR;
    int ct = t & (CTILES - 1);
    int kt = t >> 2;            // log2(CTILES) = 2
    int i  = p >> 1;
    int e  = p & 1;
    int rb = e ? (i + 1) : i;   // row block
    int cb = e ? i : (i + 1);   // col block

    int k0 = rb * BLK + kt * K_TILE;
    int n0 = cb * BLK + ct * N_TILE;

    // Stage rho for this k-tile: [K_TILE][8] floats = K_TILE*2 float4s (contiguous)
    __shared__ float4 rho_sh[K_TILE * 2];
    int tid = threadIdx.x;
    {
        const float4* rsrc = reinterpret_cast<const float4*>(g_rho_t) + (size_t)k0 * 2;
        rho_sh[tid]           = rsrc[tid];
        rho_sh[tid + THREADS] = rsrc[tid + THREADS];
    }
    __syncthreads();

    int n = n0 + tid * COLS_PER_THREAD;
    const float4* Wbase =
        reinterpret_cast<const float4*>(W + (size_t)k0 * D) + (n >> 2);

    float acc[B * COLS_PER_THREAD];
    #pragma unroll
    for (int q = 0; q < B * COLS_PER_THREAD; q++) acc[q] = 0.0f;

    #pragma unroll 4
    for (int k = 0; k < K_TILE; k++) {
        float4 w = Wbase[(size_t)k * (D / 4)];  // 4 consecutive columns, row k
        float wf[4];
        *reinterpret_cast<float4*>(wf) = w;

        float rr[8];
        *reinterpret_cast<float4*>(&rr[0]) = rho_sh[2 * k];
        *reinterpret_cast<float4*>(&rr[4]) = rho_sh[2 * k + 1];

        #pragma unroll
        for (int b2 = 0; b2 < B; b2++) {
            #pragma unroll
            for (int c = 0; c < COLS_PER_THREAD; c++) {
                acc[b2 * COLS_PER_THREAD + c] = fmaf(rr[b2], wf[c],
                                                     acc[b2 * COLS_PER_THREAD + c]);
            }
        }
    }

    // Flush partials (distinct addresses within the CTA; <=32 colliders per
    // address across k-tiles over the kernel lifetime -> negligible L2 cost)
    #pragma unroll
    for (int b2 = 0; b2 < B; b2++) {
        #pragma unroll
        for (int c = 0; c < COLS_PER_THREAD; c++) {
            atomicAdd(&g_acc[(size_t)b2 * D + n + c], acc[b2 * COLS_PER_THREAD + c]);
        }
    }
}

// ---------------------------------------------------------------------------
// Kernel 3: gate by rho'(s) = 4*rho*(1-rho)
// ---------------------------------------------------------------------------
__global__ void epilogue_kernel(const float* __restrict__ s,
                                float* __restrict__ out) {
    int idx = blockIdx.x * blockDim.x + threadIdx.x;
    if (idx >= B * D) return;
    float sv = s[idx];
    float r  = 1.0f / (1.0f + expf(-4.0f * (sv - 0.5f)));
    float rd = 4.0f * r * (1.0f - r);
    out[idx] = g_acc[idx] * rd;
}

// ---------------------------------------------------------------------------
// Launch: inputs in metadata order = Ux [8,4096], s [8,16384],
//         W [16384,16384], b [1,16384]; output [8,16384] float32.
// ---------------------------------------------------------------------------
extern "C" void kernel_launch(void* const* d_in, const int* in_sizes, int n_in,
                              void* d_out, int out_size) {
    const float* Ux   = (const float*)d_in[0];
    const float* s    = (const float*)d_in[1];
    const float* W    = (const float*)d_in[2];
    const float* bias = (const float*)d_in[3];
    float* out = (float*)d_out;

    (void)in_sizes; (void)n_in; (void)out_size;

    const int n_elem = B * D;
    prologue_kernel<<<(n_elem + 255) / 256, 256>>>(Ux, s, bias);
    gemv_kernel<<<GEMV_GRID, THREADS>>>(W);
    epilogue_kernel<<<(n_elem + 255) / 256, 256>>>(s, out);
}

// round 2
// speedup vs baseline: 1.0787x; 1.0787x over previous
#include <cuda_runtime.h>
#include <math.h>
#include <stdint.h>

// Problem constants (fixed by the reference: HIDDEN_LAYERS = [4096]*4)
#define D    16384
#define B    8
#define H0   4096
#define BLK  4096

// GEMV tiling
#define K_TILE   256
#define THREADS  256
#define COLS_PER_THREAD 4
#define N_TILE   (THREADS * COLS_PER_THREAD)   // 1024
#define CTILES   (BLK / N_TILE)                // 4
#define KTILES   (BLK / K_TILE)                // 16
#define TILES_PER_PAIR (CTILES * KTILES)       // 64
#define NUM_PAIRS 6
#define GEMV_GRID (NUM_PAIRS * TILES_PER_PAIR) // 384

// Accumulator scratch, TRANSPOSED layout: g_acc[d][b] so each output column's
// 8 batch partials are contiguous (16B-aligned pairs for red.v4).
__device__ __align__(16) float g_acc[D * B];

// ---------------------------------------------------------------------------
// fast sigmoid(4*(x-0.5)) = 1/(1+exp(2-4x))
// ---------------------------------------------------------------------------
__device__ __forceinline__ float rho_fast(float sv) {
    return __fdividef(1.0f, 1.0f + __expf(2.0f - 4.0f * sv));
}

// packed f32x2 helpers (sm_100+)
__device__ __forceinline__ unsigned long long pack2(float lo, float hi) {
    unsigned long long r;
    asm("mov.b64 %0, {%1, %2};" : "=l"(r) : "f"(lo), "f"(hi));
    return r;
}
__device__ __forceinline__ void fma2(unsigned long long& d,
                                     unsigned long long a,
                                     unsigned long long b) {
    asm("fma.rn.f32x2 %0, %1, %2, %0;" : "+l"(d) : "l"(a), "l"(b));
}
__device__ __forceinline__ void unpack2(unsigned long long v, float& lo, float& hi) {
    asm("mov.b64 {%0, %1}, %2;" : "=f"(lo), "=f"(hi) : "l"(v));
}
__device__ __forceinline__ void red_add_v4(float* ptr, float a, float b,
                                           float c, float d) {
    asm volatile("red.global.add.v4.f32 [%0], {%1, %2, %3, %4};"
                 :: "l"(ptr), "f"(a), "f"(b), "f"(c), "f"(d) : "memory");
}

// ---------------------------------------------------------------------------
// Kernel 1: accumulator init  g_acc[d][b] = bias[d] + (d < H0 ? Ux[b][d] : 0)
// ---------------------------------------------------------------------------
__global__ void init_kernel(const float* __restrict__ Ux,
                            const float* __restrict__ bias) {
    int idx = blockIdx.x * blockDim.x + threadIdx.x;  // = d*8 + b
    if (idx >= D * B) return;
    int d = idx >> 3;
    int b = idx & 7;
    float a = bias[d];
    if (d < H0) a += Ux[b * H0 + d];
    g_acc[idx] = a;   // coalesced write
}

// ---------------------------------------------------------------------------
// Kernel 2: block-sparse batched GEMV mainloop (f32x2 packed over batch)
//   acc[d=n][b] += sum_k rho(s[b][k]) * W[k, n]  over 6 nonzero 4096^2 blocks
// ---------------------------------------------------------------------------
__global__ void __launch_bounds__(THREADS)
gemv_kernel(const float* __restrict__ W, const float* __restrict__ s) {
    // Decode tile: pair p -> (rb, cb), then column tile ct, k tile kt
    int bid = blockIdx.x;
    int p = bid / TILES_PER_PAIR;
    int t = bid - p * TILES_PER_PAIR;
    int ct = t & (CTILES - 1);
    int kt = t >> 2;            // log2(CTILES) = 2
    int i  = p >> 1;
    int e  = p & 1;
    int rb = e ? (i + 1) : i;   // row block (rho side)
    int cb = e ? i : (i + 1);   // col block (output side)

    int k0 = rb * BLK + kt * K_TILE;
    int n0 = cb * BLK + ct * N_TILE;
    int tid = threadIdx.x;

    // Compute rho for this k-strip directly from s (coalesced per batch row).
    // Layout rho_sh[k][b]: 8 consecutive floats per k -> natural b-pairs.
    __shared__ __align__(16) float rho_sh[K_TILE * B];
    #pragma unroll
    for (int b = 0; b < B; b++) {
        float sv = s[(size_t)b * D + k0 + tid];
        rho_sh[tid * B + b] = rho_fast(sv);
    }
    __syncthreads();

    int n = n0 + tid * COLS_PER_THREAD;
    const float4* Wbase =
        reinterpret_cast<const float4*>(W + (size_t)k0 * D + n);
    const ulonglong2* rsh = reinterpret_cast<const ulonglong2*>(rho_sh);

    // acc[c][pair]: packed (b=2p, b=2p+1) accumulators
    unsigned long long acc[COLS_PER_THREAD * 4];
    #pragma unroll
    for (int q = 0; q < COLS_PER_THREAD * 4; q++) acc[q] = 0ULL;

    #pragma unroll 8
    for (int k = 0; k < K_TILE; k++) {
        float4 w = Wbase[(size_t)k * (D / 4)];   // 4 consecutive cols, row k

        ulonglong2 ra = rsh[2 * k];              // pairs (b0,b1), (b2,b3)
        ulonglong2 rbp = rsh[2 * k + 1];         // pairs (b4,b5), (b6,b7)

        unsigned long long ww0 = pack2(w.x, w.x);
        unsigned long long ww1 = pack2(w.y, w.y);
        unsigned long long ww2 = pack2(w.z, w.z);
        unsigned long long ww3 = pack2(w.w, w.w);

        fma2(acc[0 * 4 + 0], ww0, ra.x);  fma2(acc[0 * 4 + 1], ww0, ra.y);
        fma2(acc[0 * 4 + 2], ww0, rbp.x); fma2(acc[0 * 4 + 3], ww0, rbp.y);
        fma2(acc[1 * 4 + 0], ww1, ra.x);  fma2(acc[1 * 4 + 1], ww1, ra.y);
        fma2(acc[1 * 4 + 2], ww1, rbp.x); fma2(acc[1 * 4 + 3], ww1, rbp.y);
        fma2(acc[2 * 4 + 0], ww2, ra.x);  fma2(acc[2 * 4 + 1], ww2, ra.y);
        fma2(acc[2 * 4 + 2], ww2, rbp.x); fma2(acc[2 * 4 + 3], ww2, rbp.y);
        fma2(acc[3 * 4 + 0], ww3, ra.x);  fma2(acc[3 * 4 + 1], ww3, ra.y);
        fma2(acc[3 * 4 + 2], ww3, rbp.x); fma2(acc[3 * 4 + 3], ww3, rbp.y);
    }

    // Flush partials: per column, 8 contiguous batch slots -> 2x red.v4.f32
    #pragma unroll
    for (int c = 0; c < COLS_PER_THREAD; c++) {
        float v0, v1, v2, v3, v4, v5, v6, v7;
        unpack2(acc[c * 4 + 0], v0, v1);
        unpack2(acc[c * 4 + 1], v2, v3);
        unpack2(acc[c * 4 + 2], v4, v5);
        unpack2(acc[c * 4 + 3], v6, v7);
        float* ptr = g_acc + (size_t)(n + c) * B;   // 32B-aligned
        red_add_v4(ptr,     v0, v1, v2, v3);
        red_add_v4(ptr + 4, v4, v5, v6, v7);
    }
}

// ---------------------------------------------------------------------------
// Kernel 3: gate by rho'(s) = 4*rho*(1-rho)
//   out[b][d] = g_acc[d][b] * rhod(s[b][d])
// ---------------------------------------------------------------------------
__global__ void epilogue_kernel(const float* __restrict__ s,
                                float* __restrict__ out) {
    int idx = blockIdx.x * blockDim.x + threadIdx.x;  // = b*D + d
    if (idx >= B * D) return;
    int b = idx >> 14;        // /D
    int d = idx & (D - 1);
    float r  = rho_fast(s[idx]);
    float rd = 4.0f * r * (1.0f - r);
    out[idx] = g_acc[d * B + b] * rd;
}

// ---------------------------------------------------------------------------
// Launch: inputs in metadata order = Ux [8,4096], s [8,16384],
//         W [16384,16384], b [1,16384]; output [8,16384] float32.
// ---------------------------------------------------------------------------
extern "C" void kernel_launch(void* const* d_in, const int* in_sizes, int n_in,
                              void* d_out, int out_size) {
    const float* Ux   = (const float*)d_in[0];
    const float* s    = (const float*)d_in[1];
    const float* W    = (const float*)d_in[2];
    const float* bias = (const float*)d_in[3];
    float* out = (float*)d_out;

    (void)in_sizes; (void)n_in; (void)out_size;

    const int n_elem = B * D;
    init_kernel<<<(n_elem + 255) / 256, 256>>>(Ux, bias);
    gemv_kernel<<<GEMV_GRID, THREADS>>>(W, s);
    epilogue_kernel<<<(n_elem + 255) / 256, 256>>>(s, out);
}